// round 1
// baseline (speedup 1.0000x reference)
#include <cuda_runtime.h>
#include <cuda_bf16.h>
#include <math.h>

// Problem constants
#define TX 64
#define BB 64
#define TY 32
#define EE 256
#define HH 512
#define H3 1536
#define KY 32000
#define CTXD 1024      // 2H
#define RNNIN 1280     // E + 2H

// ---------------- device scratch (static globals; no allocation) ----------------
__device__ float g_gi_f[TX * BB * H3];        // input-side GRU preacts, forward
__device__ float g_gi_b[TX * BB * H3];        // backward
__device__ float g_henc[2][2][BB * HH];       // [dir][parity] encoder hidden
__device__ float g_enc[TX * BB * CTXD];       // encoder outputs [t][b][2H]
__device__ float g_P[TX * BB * HH];           // enc_output @ W_a1[:,H:]^T + b_a1
__device__ float g_hd[2][BB * HH];            // decoder hidden double buffer
__device__ float g_q[BB * HH];                // h @ W_a1[:, :H]^T
__device__ float g_lin[BB * H3];              // [h2, context] for logits GEMM
__device__ float g_rnnin[BB * RNNIN];         // [emb, context]
__device__ int   g_tok[BB];

__device__ __forceinline__ float sigm(float x) { return 1.0f / (1.0f + expf(-x)); }

// ---------------- init ----------------
__global__ void init_kernel() {
    int i = blockIdx.x * blockDim.x + threadIdx.x;
    if (i < BB * HH) {
        g_henc[0][0][i] = 0.f;
        g_henc[1][0][i] = 0.f;
    }
    if (i < BB) g_tok[i] = 1;
}

// ---------------- generic SGEMM: C[M,N] = A@W^T + bias ----------------
// A: M x K row-major (lda=K), optional row gather. W: N x K row-major (ldw).
// Tiles: BM=64, BN=128, BK=16. 256 threads, 4x8 microtile.
__global__ __launch_bounds__(256) void sgemm_kernel(
    const float* __restrict__ A, const int* __restrict__ gather,
    const float* __restrict__ W, int ldw,
    const float* __restrict__ bias,
    float* __restrict__ C, int N, int K)
{
    __shared__ float As[16][64];
    __shared__ float Ws[16][128];
    int tid = threadIdx.x;
    int m0 = blockIdx.y * 64;
    int n0 = blockIdx.x * 128;
    int tx = tid & 15, ty = tid >> 4;

    float acc[4][8];
#pragma unroll
    for (int i = 0; i < 4; i++)
#pragma unroll
        for (int j = 0; j < 8; j++) acc[i][j] = 0.f;

    int lrow = tid >> 2;         // 0..63
    int lk = (tid & 3) * 4;      // 0,4,8,12
    int arow = m0 + lrow;
    int aphys = gather ? gather[arow] : arow;
    const float* Aptr = A + (size_t)aphys * K + lk;

    for (int k0 = 0; k0 < K; k0 += 16) {
        float4 av = *(const float4*)(Aptr + k0);
        As[lk + 0][lrow] = av.x; As[lk + 1][lrow] = av.y;
        As[lk + 2][lrow] = av.z; As[lk + 3][lrow] = av.w;
#pragma unroll
        for (int r = 0; r < 2; r++) {
            int nrow = lrow + r * 64;
            float4 wv = *(const float4*)(W + (size_t)(n0 + nrow) * ldw + k0 + lk);
            Ws[lk + 0][nrow] = wv.x; Ws[lk + 1][nrow] = wv.y;
            Ws[lk + 2][nrow] = wv.z; Ws[lk + 3][nrow] = wv.w;
        }
        __syncthreads();
#pragma unroll
        for (int kk = 0; kk < 16; kk++) {
            float a[4];
#pragma unroll
            for (int i = 0; i < 4; i++) a[i] = As[kk][ty * 4 + i];
            float4 b0 = *(const float4*)&Ws[kk][tx * 8];
            float4 b1 = *(const float4*)&Ws[kk][tx * 8 + 4];
            float bb8[8] = { b0.x, b0.y, b0.z, b0.w, b1.x, b1.y, b1.z, b1.w };
#pragma unroll
            for (int i = 0; i < 4; i++)
#pragma unroll
                for (int j = 0; j < 8; j++) acc[i][j] += a[i] * bb8[j];
        }
        __syncthreads();
    }
#pragma unroll
    for (int i = 0; i < 4; i++) {
        int m = m0 + ty * 4 + i;
        float* crow = C + (size_t)m * N + n0 + tx * 8;
#pragma unroll
        for (int j = 0; j < 8; j++) {
            float v = acc[i][j];
            if (bias) v += bias[n0 + tx * 8 + j];
            crow[j] = v;
        }
    }
}

// ---------------- encoder GRU step (both directions in one launch) ----------------
// grid: (64 j-tiles, 2 dirs), 512 threads = (b 0..63) x (jl 0..7)
__global__ __launch_bounds__(512) void enc_step_kernel(
    int t,
    const float* __restrict__ Whh_f, const float* __restrict__ bhh_f,
    const float* __restrict__ Whh_b, const float* __restrict__ bhh_b)
{
    __shared__ float hs[128][65];
    __shared__ float ws[24][128];

    int dir = blockIdx.y;
    int par = t & 1;
    const float* Whh = dir ? Whh_b : Whh_f;
    const float* bhh = dir ? bhh_b : bhh_f;
    int row = dir ? (TX - 1 - t) : t;
    const float* gi = (dir ? g_gi_b : g_gi_f) + (size_t)row * BB * H3;
    const float* hin = g_henc[dir][par];
    float* hout = g_henc[dir][par ^ 1];
    int colofs = dir ? HH : 0;

    int tid = threadIdx.x;
    int b = tid & 63;
    int jl = tid >> 6;       // 0..7
    int j0 = blockIdx.x * 8;
    int j = j0 + jl;

    float dr = 0.f, dz = 0.f, dn = 0.f;
    for (int kb = 0; kb < 4; kb++) {
        int kbase = kb * 128;
#pragma unroll
        for (int r = 0; r < 16; r++) {
            int i = tid + r * 512;
            int kk = i & 127, bb2 = i >> 7;
            hs[kk][bb2] = hin[bb2 * HH + kbase + kk];
        }
#pragma unroll
        for (int r = 0; r < 6; r++) {
            int i = tid + r * 512;
            int kk = i & 127, rr = i >> 7;
            int g = rr >> 3, jloc = rr & 7;
            ws[rr][kk] = Whh[(g * HH + j0 + jloc) * HH + kbase + kk];
        }
        __syncthreads();
#pragma unroll 8
        for (int k = 0; k < 128; k += 4) {
            float4 wr = *(const float4*)&ws[jl][k];
            float4 wz = *(const float4*)&ws[8 + jl][k];
            float4 wn = *(const float4*)&ws[16 + jl][k];
            float h0 = hs[k][b], h1 = hs[k + 1][b], h2v = hs[k + 2][b], h3v = hs[k + 3][b];
            dr += h0 * wr.x + h1 * wr.y + h2v * wr.z + h3v * wr.w;
            dz += h0 * wz.x + h1 * wz.y + h2v * wz.z + h3v * wz.w;
            dn += h0 * wn.x + h1 * wn.y + h2v * wn.z + h3v * wn.w;
        }
        __syncthreads();
    }

    const float* girow = gi + b * H3;
    float r = sigm(girow[j] + dr + bhh[j]);
    float z = sigm(girow[HH + j] + dz + bhh[HH + j]);
    float n = tanhf(girow[2 * HH + j] + r * (dn + bhh[2 * HH + j]));
    float hold = hin[b * HH + j];
    float h2 = (1.f - z) * n + z * hold;
    hout[b * HH + j] = h2;
    g_enc[(size_t)(row * BB + b) * CTXD + colofs + j] = h2;
}

// ---------------- column projection: dst[b,j] = act(src[b,:]@Wrow_j + bias) ----------------
// K=512 fixed. grid 64 (j-tiles of 8), 512 threads.
__global__ __launch_bounds__(512) void colproj_kernel(
    const float* __restrict__ src, const float* __restrict__ W, int ldw,
    const float* __restrict__ bias, float* __restrict__ dst, int act)
{
    __shared__ float hs[128][65];
    __shared__ float ws[8][128];
    int tid = threadIdx.x;
    int b = tid & 63;
    int jl = tid >> 6;
    int j0 = blockIdx.x * 8;
    int j = j0 + jl;

    float acc = 0.f;
    for (int kb = 0; kb < 4; kb++) {
        int kbase = kb * 128;
#pragma unroll
        for (int r = 0; r < 16; r++) {
            int i = tid + r * 512;
            int kk = i & 127, bb2 = i >> 7;
            hs[kk][bb2] = src[bb2 * HH + kbase + kk];
        }
#pragma unroll
        for (int r = 0; r < 2; r++) {
            int i = tid + r * 512;
            int kk = i & 127, rr = i >> 7;
            ws[rr][kk] = W[(size_t)(j0 + rr) * ldw + kbase + kk];
        }
        __syncthreads();
#pragma unroll 8
        for (int k = 0; k < 128; k += 4) {
            float4 wv = *(const float4*)&ws[jl][k];
            acc += hs[k][b] * wv.x + hs[k + 1][b] * wv.y
                 + hs[k + 2][b] * wv.z + hs[k + 3][b] * wv.w;
        }
        __syncthreads();
    }
    if (bias) acc += bias[j];
    if (act) acc = tanhf(acc);
    dst[b * HH + j] = acc;
}

// ---------------- attention (per decoder step): scores + softmax + context ----------------
// grid 64 (one CTA per batch b), 256 threads
__global__ __launch_bounds__(256) void attn_kernel(
    const float* __restrict__ W_a2, const float* __restrict__ b_a2)
{
    __shared__ float qs[HH];
    __shared__ float was[HH];
    __shared__ float ss[TX];
    __shared__ float wgt[TX];

    int b = blockIdx.x;
    int tid = threadIdx.x;
    int lane = tid & 31;
    int warp = tid >> 5;

    for (int i = tid; i < HH; i += 256) {
        qs[i] = g_q[b * HH + i];
        was[i] = W_a2[i];
    }
    __syncthreads();

    // scores: each warp handles 8 t's
    for (int tt = 0; tt < 8; tt++) {
        int t = warp * 8 + tt;
        const float* Prow = g_P + (size_t)(t * BB + b) * HH;
        float p = 0.f;
#pragma unroll 4
        for (int jj = lane; jj < HH; jj += 32)
            p += was[jj] * tanhf(qs[jj] + Prow[jj]);
#pragma unroll
        for (int o = 16; o > 0; o >>= 1)
            p += __shfl_down_sync(0xffffffffu, p, o);
        if (lane == 0) ss[t] = p + b_a2[0];
    }
    __syncthreads();

    // softmax over t (single warp)
    if (tid < 32) {
        float v0 = ss[tid], v1 = ss[tid + 32];
        float m = fmaxf(v0, v1);
#pragma unroll
        for (int o = 16; o > 0; o >>= 1)
            m = fmaxf(m, __shfl_xor_sync(0xffffffffu, m, o));
        float e0 = expf(v0 - m), e1 = expf(v1 - m);
        float s = e0 + e1;
#pragma unroll
        for (int o = 16; o > 0; o >>= 1)
            s += __shfl_xor_sync(0xffffffffu, s, o);
        wgt[tid] = e0 / s;
        wgt[tid + 32] = e1 / s;
    }
    __syncthreads();

    // context over 2H, write into logits-A and rnn input
    for (int i = tid; i < CTXD; i += 256) {
        float c = 0.f;
#pragma unroll 8
        for (int t = 0; t < TX; t++)
            c += wgt[t] * g_enc[(size_t)(t * BB + b) * CTXD + i];
        g_lin[b * H3 + HH + i] = c;
        g_rnnin[b * RNNIN + EE + i] = c;
    }
}

// ---------------- embedding lookup ----------------
__global__ void embed_kernel(const float* __restrict__ dec_emb)
{
    int b = blockIdx.x;
    int tok = g_tok[b];
    for (int i = threadIdx.x; i < EE; i += blockDim.x)
        g_rnnin[b * RNNIN + i] = dec_emb[(size_t)tok * EE + i];
}

// ---------------- decoder GRU (fused input+hidden GEMM + gates) ----------------
// grid 128 (j-tiles of 4), 256 threads = (b 0..63) x (jl 0..3)
__global__ __launch_bounds__(256) void decgru_kernel(
    int s,
    const float* __restrict__ Wih, const float* __restrict__ Whh,
    const float* __restrict__ bih, const float* __restrict__ bhh)
{
    __shared__ float xs[128][65];
    __shared__ float ws[12][128];

    int tid = threadIdx.x;
    int b = tid & 63;
    int jl = tid >> 6;      // 0..3
    int j0 = blockIdx.x * 4;
    int j = j0 + jl;
    int par = s & 1;
    const float* hin = g_hd[par];
    float* hout = g_hd[par ^ 1];

    float ar = 0.f, az = 0.f, anx = 0.f, anh = 0.f;

    // phase 1: x @ W_ih^T, K = 1280
    for (int kb = 0; kb < 10; kb++) {
        int kbase = kb * 128;
#pragma unroll
        for (int r = 0; r < 32; r++) {
            int i = tid + r * 256;
            int kk = i & 127, bb2 = i >> 7;
            xs[kk][bb2] = g_rnnin[bb2 * RNNIN + kbase + kk];
        }
#pragma unroll
        for (int r = 0; r < 6; r++) {
            int i = tid + r * 256;
            int kk = i & 127, rr = i >> 7;
            int g = rr >> 2, jloc = rr & 3;
            ws[rr][kk] = Wih[(size_t)(g * HH + j0 + jloc) * RNNIN + kbase + kk];
        }
        __syncthreads();
#pragma unroll 8
        for (int k = 0; k < 128; k += 4) {
            float4 wr = *(const float4*)&ws[jl][k];
            float4 wz = *(const float4*)&ws[4 + jl][k];
            float4 wn = *(const float4*)&ws[8 + jl][k];
            float x0 = xs[k][b], x1 = xs[k + 1][b], x2 = xs[k + 2][b], x3 = xs[k + 3][b];
            ar += x0 * wr.x + x1 * wr.y + x2 * wr.z + x3 * wr.w;
            az += x0 * wz.x + x1 * wz.y + x2 * wz.z + x3 * wz.w;
            anx += x0 * wn.x + x1 * wn.y + x2 * wn.z + x3 * wn.w;
        }
        __syncthreads();
    }

    // phase 2: h @ W_hh^T, K = 512
    for (int kb = 0; kb < 4; kb++) {
        int kbase = kb * 128;
#pragma unroll
        for (int r = 0; r < 32; r++) {
            int i = tid + r * 256;
            int kk = i & 127, bb2 = i >> 7;
            xs[kk][bb2] = hin[bb2 * HH + kbase + kk];
        }
#pragma unroll
        for (int r = 0; r < 6; r++) {
            int i = tid + r * 256;
            int kk = i & 127, rr = i >> 7;
            int g = rr >> 2, jloc = rr & 3;
            ws[rr][kk] = Whh[(size_t)(g * HH + j0 + jloc) * HH + kbase + kk];
        }
        __syncthreads();
#pragma unroll 8
        for (int k = 0; k < 128; k += 4) {
            float4 wr = *(const float4*)&ws[jl][k];
            float4 wz = *(const float4*)&ws[4 + jl][k];
            float4 wn = *(const float4*)&ws[8 + jl][k];
            float x0 = xs[k][b], x1 = xs[k + 1][b], x2 = xs[k + 2][b], x3 = xs[k + 3][b];
            ar += x0 * wr.x + x1 * wr.y + x2 * wr.z + x3 * wr.w;
            az += x0 * wz.x + x1 * wz.y + x2 * wz.z + x3 * wz.w;
            anh += x0 * wn.x + x1 * wn.y + x2 * wn.z + x3 * wn.w;
        }
        __syncthreads();
    }

    float r = sigm(ar + bih[j] + bhh[j]);
    float z = sigm(az + bih[HH + j] + bhh[HH + j]);
    float n = tanhf(anx + bih[2 * HH + j] + r * (anh + bhh[2 * HH + j]));
    float hold = hin[b * HH + j];
    float h2 = (1.f - z) * n + z * hold;
    hout[b * HH + j] = h2;
    g_lin[b * H3 + j] = h2;
}

// ---------------- log-softmax + argmax (per decoder step), in place ----------------
// grid 64, 256 threads
__global__ __launch_bounds__(256) void lsm_kernel(float* __restrict__ out, int step)
{
    __shared__ float rm[256];
    __shared__ int ri[256];
    __shared__ float rs[256];

    int b = blockIdx.x;
    int tid = threadIdx.x;
    float* row = out + (size_t)(step * BB + b) * KY;

    float m = -1e30f; int mi = 0;
    for (int i = tid; i < KY; i += 256) {
        float v = row[i];
        if (v > m) { m = v; mi = i; }
    }
    rm[tid] = m; ri[tid] = mi;
    __syncthreads();
    for (int o = 128; o > 0; o >>= 1) {
        if (tid < o) {
            float vb = rm[tid + o]; int ib = ri[tid + o];
            if (vb > rm[tid] || (vb == rm[tid] && ib < ri[tid])) { rm[tid] = vb; ri[tid] = ib; }
        }
        __syncthreads();
    }
    float M = rm[0];
    int Mi = ri[0];

    float s = 0.f;
    for (int i = tid; i < KY; i += 256) s += expf(row[i] - M);
    rs[tid] = s;
    __syncthreads();
    for (int o = 128; o > 0; o >>= 1) {
        if (tid < o) rs[tid] += rs[tid + o];
        __syncthreads();
    }
    float lse = M + logf(rs[0]);

    for (int i = tid; i < KY; i += 256) row[i] = row[i] - lse;
    if (tid == 0) g_tok[b] = Mi;
}

// ---------------- host launch ----------------
extern "C" void kernel_launch(void* const* d_in, const int* in_sizes, int n_in,
                              void* d_out, int out_size)
{
    const int*   inputs  = (const int*)d_in[0];
    const float* enc_emb = (const float*)d_in[2];
    const float* W_ih_f  = (const float*)d_in[3];
    const float* W_hh_f  = (const float*)d_in[4];
    const float* b_ih_f  = (const float*)d_in[5];
    const float* b_hh_f  = (const float*)d_in[6];
    const float* W_ih_b  = (const float*)d_in[7];
    const float* W_hh_b  = (const float*)d_in[8];
    const float* b_ih_b  = (const float*)d_in[9];
    const float* b_hh_b  = (const float*)d_in[10];
    const float* W_init  = (const float*)d_in[11];
    const float* b_init  = (const float*)d_in[12];
    const float* dec_emb = (const float*)d_in[13];
    const float* W_ih_d  = (const float*)d_in[14];
    const float* W_hh_d  = (const float*)d_in[15];
    const float* b_ih_d  = (const float*)d_in[16];
    const float* b_hh_d  = (const float*)d_in[17];
    const float* W_lsm   = (const float*)d_in[18];
    const float* b_lsm   = (const float*)d_in[19];
    const float* W_a1    = (const float*)d_in[20];
    const float* b_a1    = (const float*)d_in[21];
    const float* W_a2    = (const float*)d_in[22];
    const float* b_a2    = (const float*)d_in[23];
    float* out = (float*)d_out;

    static float* p_gi_f = nullptr;
    static float* p_gi_b = nullptr;
    static float* p_enc  = nullptr;
    static float* p_P    = nullptr;
    static float* p_lin  = nullptr;
    static float* p_hd   = nullptr;
    static float* p_henc = nullptr;
    static float* p_q    = nullptr;
    if (!p_gi_f) {
        cudaGetSymbolAddress((void**)&p_gi_f, g_gi_f);
        cudaGetSymbolAddress((void**)&p_gi_b, g_gi_b);
        cudaGetSymbolAddress((void**)&p_enc,  g_enc);
        cudaGetSymbolAddress((void**)&p_P,    g_P);
        cudaGetSymbolAddress((void**)&p_lin,  g_lin);
        cudaGetSymbolAddress((void**)&p_hd,   g_hd);
        cudaGetSymbolAddress((void**)&p_henc, g_henc);
        cudaGetSymbolAddress((void**)&p_q,    g_q);
    }

    init_kernel<<<128, 256>>>();

    // batched input-side GRU preactivations (gathered embeddings): M=4096, N=1536, K=256
    sgemm_kernel<<<dim3(H3 / 128, TX * BB / 64), 256>>>(
        enc_emb, inputs, W_ih_f, EE, b_ih_f, p_gi_f, H3, EE);
    sgemm_kernel<<<dim3(H3 / 128, TX * BB / 64), 256>>>(
        enc_emb, inputs, W_ih_b, EE, b_ih_b, p_gi_b, H3, EE);

    // encoder recurrence (both directions per launch)
    for (int t = 0; t < TX; t++)
        enc_step_kernel<<<dim3(64, 2), 512>>>(t, W_hh_f, b_hh_f, W_hh_b, b_hh_b);

    // step-invariant attention term: P = enc_output @ W_a1[:, H:]^T + b_a1
    sgemm_kernel<<<dim3(HH / 128, TX * BB / 64), 256>>>(
        p_enc, nullptr, W_a1 + HH, H3, b_a1, p_P, HH, CTXD);

    // decoder hidden init: tanh(h_b_final @ W_init^T + b_init) -> g_hd[0]
    // final backward hidden lives in g_henc[1][0] (t=63 writes parity 0)
    colproj_kernel<<<64, 512>>>(p_henc + 2 * BB * HH, W_init, HH, b_init, p_hd, 1);

    for (int s = 0; s < TY; s++) {
        float* hcur = p_hd + (s & 1) * BB * HH;
        colproj_kernel<<<64, 512>>>(hcur, W_a1, H3, nullptr, p_q, 0);
        embed_kernel<<<64, 256>>>(dec_emb);
        attn_kernel<<<64, 256>>>(W_a2, b_a2);
        decgru_kernel<<<128, 256>>>(s, W_ih_d, W_hh_d, b_ih_d, b_hh_d);
        sgemm_kernel<<<dim3(KY / 128, 1), 256>>>(
            p_lin, nullptr, W_lsm, H3, b_lsm,
            out + (size_t)s * BB * KY, KY, H3);
        lsm_kernel<<<64, 256>>>(out, s);
    }
}

// round 3
// speedup vs baseline: 1.9201x; 1.9201x over previous
#include <cuda_runtime.h>
#include <cuda_bf16.h>
#include <math.h>
#include <stdint.h>

// Problem constants
#define TX 64
#define BB 64
#define TY 32
#define EE 256
#define HH 512
#define H3 1536
#define KY 32000
#define CTXD 1024      // 2H
#define RNNIN 1280     // E + 2H

// ---------------- device scratch (static globals; no allocation) ----------------
__device__ float g_gi_f[TX * BB * H3];
__device__ float g_gi_b[TX * BB * H3];
__device__ float g_henc[2][2][BB * HH];
__device__ float g_enc[TX * BB * CTXD];
__device__ float g_P[TX * BB * HH];
__device__ float g_hd[2][BB * HH];
__device__ float g_q[BB * HH];
__device__ float g_lin[BB * H3];
__device__ float g_rnnin[BB * RNNIN];
__device__ int   g_tok[BB];

// bf16 split copies for tensor-core logits GEMM
__device__ __nv_bfloat16 g_wh[(size_t)KY * H3];   // hi(W_lsm)
__device__ __nv_bfloat16 g_wl[(size_t)KY * H3];   // lo(W_lsm)
__device__ __nv_bfloat16 g_ah[BB * H3];           // hi(g_lin)
__device__ __nv_bfloat16 g_al[BB * H3];           // lo(g_lin)

__device__ __forceinline__ float sigm(float x) { return 1.0f / (1.0f + expf(-x)); }

// ---------------- init ----------------
__global__ void init_kernel() {
    int i = blockIdx.x * blockDim.x + threadIdx.x;
    if (i < BB * HH) {
        g_henc[0][0][i] = 0.f;
        g_henc[1][0][i] = 0.f;
    }
    if (i < BB) g_tok[i] = 1;
}

// ---------------- W_lsm -> bf16 hi/lo split (once per launch) ----------------
__global__ __launch_bounds__(256) void convw_kernel(const float* __restrict__ W) {
    size_t i = (size_t)blockIdx.x * blockDim.x + threadIdx.x;  // over KY*H3/4
    const float4* W4 = (const float4*)W;
    float4 v = W4[i];
    __nv_bfloat16 h0 = __float2bfloat16(v.x);
    __nv_bfloat16 h1 = __float2bfloat16(v.y);
    __nv_bfloat16 h2 = __float2bfloat16(v.z);
    __nv_bfloat16 h3 = __float2bfloat16(v.w);
    __nv_bfloat16 l0 = __float2bfloat16(v.x - __bfloat162float(h0));
    __nv_bfloat16 l1 = __float2bfloat16(v.y - __bfloat162float(h1));
    __nv_bfloat16 l2 = __float2bfloat16(v.z - __bfloat162float(h2));
    __nv_bfloat16 l3 = __float2bfloat16(v.w - __bfloat162float(h3));
    __nv_bfloat162* H2 = reinterpret_cast<__nv_bfloat162*>(g_wh);
    __nv_bfloat162* L2 = reinterpret_cast<__nv_bfloat162*>(g_wl);
    H2[2 * i]     = __nv_bfloat162{h0, h1};
    H2[2 * i + 1] = __nv_bfloat162{h2, h3};
    L2[2 * i]     = __nv_bfloat162{l0, l1};
    L2[2 * i + 1] = __nv_bfloat162{l2, l3};
}

// ---------------- g_lin -> bf16 hi/lo (per decoder step) ----------------
__global__ __launch_bounds__(256) void conva_kernel() {
    int i = blockIdx.x * blockDim.x + threadIdx.x;  // over BB*H3/4
    const float4* S4 = (const float4*)g_lin;
    float4 v = S4[i];
    __nv_bfloat16 h0 = __float2bfloat16(v.x);
    __nv_bfloat16 h1 = __float2bfloat16(v.y);
    __nv_bfloat16 h2 = __float2bfloat16(v.z);
    __nv_bfloat16 h3 = __float2bfloat16(v.w);
    __nv_bfloat16 l0 = __float2bfloat16(v.x - __bfloat162float(h0));
    __nv_bfloat16 l1 = __float2bfloat16(v.y - __bfloat162float(h1));
    __nv_bfloat16 l2 = __float2bfloat16(v.z - __bfloat162float(h2));
    __nv_bfloat16 l3 = __float2bfloat16(v.w - __bfloat162float(h3));
    __nv_bfloat162* H2 = reinterpret_cast<__nv_bfloat162*>(g_ah);
    __nv_bfloat162* L2 = reinterpret_cast<__nv_bfloat162*>(g_al);
    H2[2 * i]     = __nv_bfloat162{h0, h1};
    H2[2 * i + 1] = __nv_bfloat162{h2, h3};
    L2[2 * i]     = __nv_bfloat162{l0, l1};
    L2[2 * i + 1] = __nv_bfloat162{l2, l3};
}

// ---------------- mma.sync bf16 helper ----------------
__device__ __forceinline__ void mma16816(float* d, const uint32_t* a, uint32_t b0, uint32_t b1)
{
    asm volatile(
        "mma.sync.aligned.m16n8k16.row.col.f32.bf16.bf16.f32 "
        "{%0,%1,%2,%3}, {%4,%5,%6,%7}, {%8,%9}, {%0,%1,%2,%3};"
        : "+f"(d[0]), "+f"(d[1]), "+f"(d[2]), "+f"(d[3])
        : "r"(a[0]), "r"(a[1]), "r"(a[2]), "r"(a[3]), "r"(b0), "r"(b1));
}

// ---------------- logits GEMM via mma.sync (split bf16, fp32 accum) ----------------
// Each CTA: vocab tile of 256 rows x all 64 batch.
// D = Whi*Ahi + Whi*Alo + Wlo*Ahi.
// K chunked by 64, cp.async double-buffered. Rows padded to 144B (conflict-free).
#define LG_KC 64
#define LG_ROWB 144
#define LG_W_BYTES (256 * LG_ROWB)          // 36864 per tensor
#define LG_A_BYTES (64 * LG_ROWB)           // 9216 per tensor
#define LG_STAGE (2 * LG_W_BYTES + 2 * LG_A_BYTES)   // 92160
#define LG_SMEM_TOTAL (2 * LG_STAGE)                 // 184320

__global__ __launch_bounds__(256, 1) void logits_mma_kernel(
    const float* __restrict__ b_lsm, float* __restrict__ out, int step)
{
    extern __shared__ char smem[];
    int tid = threadIdx.x;
    int wid = tid >> 5, lane = tid & 31;
    int vb = blockIdx.x * 256;

    auto load_chunk = [&](int kc, int buf) {
        char* base = smem + buf * LG_STAGE;
        // W hi/lo: 256 rows x 64 bf16
        {
            char* dsth = base;
            char* dstl = base + LG_W_BYTES;
            const __nv_bfloat16* sh = g_wh + (size_t)vb * H3 + kc * LG_KC;
            const __nv_bfloat16* sl = g_wl + (size_t)vb * H3 + kc * LG_KC;
#pragma unroll
            for (int it = 0; it < 8; it++) {
                int idx = tid + it * 256;
                int r = idx >> 3, c = idx & 7;
                size_t gofs = (size_t)r * H3 + c * 8;
                uint32_t so = (uint32_t)(r * LG_ROWB + c * 16);
                uint32_t d1 = (uint32_t)__cvta_generic_to_shared(dsth + so);
                uint32_t d2 = (uint32_t)__cvta_generic_to_shared(dstl + so);
                asm volatile("cp.async.cg.shared.global [%0], [%1], 16;" :: "r"(d1), "l"(sh + gofs));
                asm volatile("cp.async.cg.shared.global [%0], [%1], 16;" :: "r"(d2), "l"(sl + gofs));
            }
        }
        // A hi/lo: 64 rows x 64 bf16
        {
            char* dsth = base + 2 * LG_W_BYTES;
            char* dstl = dsth + LG_A_BYTES;
            const __nv_bfloat16* sh = g_ah + kc * LG_KC;
            const __nv_bfloat16* sl = g_al + kc * LG_KC;
#pragma unroll
            for (int it = 0; it < 2; it++) {
                int idx = tid + it * 256;
                int r = idx >> 3, c = idx & 7;
                size_t gofs = (size_t)r * H3 + c * 8;
                uint32_t so = (uint32_t)(r * LG_ROWB + c * 16);
                uint32_t d1 = (uint32_t)__cvta_generic_to_shared(dsth + so);
                uint32_t d2 = (uint32_t)__cvta_generic_to_shared(dstl + so);
                asm volatile("cp.async.cg.shared.global [%0], [%1], 16;" :: "r"(d1), "l"(sh + gofs));
                asm volatile("cp.async.cg.shared.global [%0], [%1], 16;" :: "r"(d2), "l"(sl + gofs));
            }
        }
        asm volatile("cp.async.commit_group;" ::: "memory");
    };

    float acc[2][8][4];
#pragma unroll
    for (int mt = 0; mt < 2; mt++)
#pragma unroll
        for (int nt = 0; nt < 8; nt++)
#pragma unroll
            for (int i = 0; i < 4; i++) acc[mt][nt][i] = 0.f;

    int m0 = wid * 32;
    int krow = lane >> 2;          // 0..7
    int kcol4 = (lane & 3) * 4;    // byte offset of k pair within k16 (bf16*2 = 4B)

    load_chunk(0, 0);

    for (int c = 0; c < H3 / LG_KC; c++) {
        if (c + 1 < H3 / LG_KC) {
            load_chunk(c + 1, (c + 1) & 1);
            asm volatile("cp.async.wait_group 1;" ::: "memory");
        } else {
            asm volatile("cp.async.wait_group 0;" ::: "memory");
        }
        __syncthreads();

        char* base = smem + (c & 1) * LG_STAGE;
        const char* wh = base;
        const char* wl = base + LG_W_BYTES;
        const char* ab_h = base + 2 * LG_W_BYTES;
        const char* ab_l = ab_h + LG_A_BYTES;

#pragma unroll
        for (int kt = 0; kt < 4; kt++) {
            int kb = kt * 32 + kcol4;   // byte offset of this thread's k within row
            uint32_t ah[2][4], al[2][4];
#pragma unroll
            for (int mt = 0; mt < 2; mt++) {
                int ro = (m0 + mt * 16 + krow) * LG_ROWB + kb;
                ah[mt][0] = *(const uint32_t*)(wh + ro);
                ah[mt][1] = *(const uint32_t*)(wh + ro + 8 * LG_ROWB);
                ah[mt][2] = *(const uint32_t*)(wh + ro + 16);
                ah[mt][3] = *(const uint32_t*)(wh + ro + 8 * LG_ROWB + 16);
                al[mt][0] = *(const uint32_t*)(wl + ro);
                al[mt][1] = *(const uint32_t*)(wl + ro + 8 * LG_ROWB);
                al[mt][2] = *(const uint32_t*)(wl + ro + 16);
                al[mt][3] = *(const uint32_t*)(wl + ro + 8 * LG_ROWB + 16);
            }
#pragma unroll
            for (int nt = 0; nt < 8; nt++) {
                int ro = (nt * 8 + krow) * LG_ROWB + kb;
                uint32_t bh0 = *(const uint32_t*)(ab_h + ro);
                uint32_t bh1 = *(const uint32_t*)(ab_h + ro + 16);
                uint32_t bl0 = *(const uint32_t*)(ab_l + ro);
                uint32_t bl1 = *(const uint32_t*)(ab_l + ro + 16);
#pragma unroll
                for (int mt = 0; mt < 2; mt++) {
                    mma16816(acc[mt][nt], ah[mt], bh0, bh1);
                    mma16816(acc[mt][nt], ah[mt], bl0, bl1);
                    mma16816(acc[mt][nt], al[mt], bh0, bh1);
                }
            }
        }
        __syncthreads();
    }

    // epilogue: acc[mt][nt] is m16n8: c0/c1 row=lane/4, c2/c3 row+8; col=(lane&3)*2+{0,1}
    float* obase = out + (size_t)step * BB * KY;
#pragma unroll
    for (int mt = 0; mt < 2; mt++) {
#pragma unroll
        for (int h = 0; h < 2; h++) {
            int v = vb + m0 + mt * 16 + krow + h * 8;
            float bias = b_lsm[v];
#pragma unroll
            for (int nt = 0; nt < 8; nt++) {
                int b0 = nt * 8 + (lane & 3) * 2;
                obase[(size_t)b0 * KY + v]       = acc[mt][nt][h * 2 + 0] + bias;
                obase[(size_t)(b0 + 1) * KY + v] = acc[mt][nt][h * 2 + 1] + bias;
            }
        }
    }
}

// ---------------- generic SGEMM: C[M,N] = A@W^T + bias ----------------
__global__ __launch_bounds__(256) void sgemm_kernel(
    const float* __restrict__ A, const int* __restrict__ gather,
    const float* __restrict__ W, int ldw,
    const float* __restrict__ bias,
    float* __restrict__ C, int N, int K)
{
    __shared__ float As[16][64];
    __shared__ float Ws[16][128];
    int tid = threadIdx.x;
    int m0 = blockIdx.y * 64;
    int n0 = blockIdx.x * 128;
    int tx = tid & 15, ty = tid >> 4;

    float acc[4][8];
#pragma unroll
    for (int i = 0; i < 4; i++)
#pragma unroll
        for (int j = 0; j < 8; j++) acc[i][j] = 0.f;

    int lrow = tid >> 2;
    int lk = (tid & 3) * 4;
    int arow = m0 + lrow;
    int aphys = gather ? gather[arow] : arow;
    const float* Aptr = A + (size_t)aphys * K + lk;

    for (int k0 = 0; k0 < K; k0 += 16) {
        float4 av = *(const float4*)(Aptr + k0);
        As[lk + 0][lrow] = av.x; As[lk + 1][lrow] = av.y;
        As[lk + 2][lrow] = av.z; As[lk + 3][lrow] = av.w;
#pragma unroll
        for (int r = 0; r < 2; r++) {
            int nrow = lrow + r * 64;
            float4 wv = *(const float4*)(W + (size_t)(n0 + nrow) * ldw + k0 + lk);
            Ws[lk + 0][nrow] = wv.x; Ws[lk + 1][nrow] = wv.y;
            Ws[lk + 2][nrow] = wv.z; Ws[lk + 3][nrow] = wv.w;
        }
        __syncthreads();
#pragma unroll
        for (int kk = 0; kk < 16; kk++) {
            float a[4];
#pragma unroll
            for (int i = 0; i < 4; i++) a[i] = As[kk][ty * 4 + i];
            float4 b0 = *(const float4*)&Ws[kk][tx * 8];
            float4 b1 = *(const float4*)&Ws[kk][tx * 8 + 4];
            float bb8[8] = { b0.x, b0.y, b0.z, b0.w, b1.x, b1.y, b1.z, b1.w };
#pragma unroll
            for (int i = 0; i < 4; i++)
#pragma unroll
                for (int j = 0; j < 8; j++) acc[i][j] += a[i] * bb8[j];
        }
        __syncthreads();
    }
#pragma unroll
    for (int i = 0; i < 4; i++) {
        int m = m0 + ty * 4 + i;
        float* crow = C + (size_t)m * N + n0 + tx * 8;
#pragma unroll
        for (int j = 0; j < 8; j++) {
            float v = acc[i][j];
            if (bias) v += bias[n0 + tx * 8 + j];
            crow[j] = v;
        }
    }
}

// ---------------- encoder GRU step (both directions in one launch) ----------------
__global__ __launch_bounds__(512) void enc_step_kernel(
    int t,
    const float* __restrict__ Whh_f, const float* __restrict__ bhh_f,
    const float* __restrict__ Whh_b, const float* __restrict__ bhh_b)
{
    __shared__ float hs[128][65];
    __shared__ float ws[24][128];

    int dir = blockIdx.y;
    int par = t & 1;
    const float* Whh = dir ? Whh_b : Whh_f;
    const float* bhh = dir ? bhh_b : bhh_f;
    int row = dir ? (TX - 1 - t) : t;
    const float* gi = (dir ? g_gi_b : g_gi_f) + (size_t)row * BB * H3;
    const float* hin = g_henc[dir][par];
    float* hout = g_henc[dir][par ^ 1];
    int colofs = dir ? HH : 0;

    int tid = threadIdx.x;
    int b = tid & 63;
    int jl = tid >> 6;
    int j0 = blockIdx.x * 8;
    int j = j0 + jl;

    float dr = 0.f, dz = 0.f, dn = 0.f;
    for (int kb = 0; kb < 4; kb++) {
        int kbase = kb * 128;
#pragma unroll
        for (int r = 0; r < 16; r++) {
            int i = tid + r * 512;
            int kk = i & 127, bb2 = i >> 7;
            hs[kk][bb2] = hin[bb2 * HH + kbase + kk];
        }
#pragma unroll
        for (int r = 0; r < 6; r++) {
            int i = tid + r * 512;
            int kk = i & 127, rr = i >> 7;
            int g = rr >> 3, jloc = rr & 7;
            ws[rr][kk] = Whh[(g * HH + j0 + jloc) * HH + kbase + kk];
        }
        __syncthreads();
#pragma unroll 8
        for (int k = 0; k < 128; k += 4) {
            float4 wr = *(const float4*)&ws[jl][k];
            float4 wz = *(const float4*)&ws[8 + jl][k];
            float4 wn = *(const float4*)&ws[16 + jl][k];
            float h0 = hs[k][b], h1 = hs[k + 1][b], h2v = hs[k + 2][b], h3v = hs[k + 3][b];
            dr += h0 * wr.x + h1 * wr.y + h2v * wr.z + h3v * wr.w;
            dz += h0 * wz.x + h1 * wz.y + h2v * wz.z + h3v * wz.w;
            dn += h0 * wn.x + h1 * wn.y + h2v * wn.z + h3v * wn.w;
        }
        __syncthreads();
    }

    const float* girow = gi + b * H3;
    float r = sigm(girow[j] + dr + bhh[j]);
    float z = sigm(girow[HH + j] + dz + bhh[HH + j]);
    float n = tanhf(girow[2 * HH + j] + r * (dn + bhh[2 * HH + j]));
    float hold = hin[b * HH + j];
    float h2 = (1.f - z) * n + z * hold;
    hout[b * HH + j] = h2;
    g_enc[(size_t)(row * BB + b) * CTXD + colofs + j] = h2;
}

// ---------------- column projection ----------------
__global__ __launch_bounds__(512) void colproj_kernel(
    const float* __restrict__ src, const float* __restrict__ W, int ldw,
    const float* __restrict__ bias, float* __restrict__ dst, int act)
{
    __shared__ float hs[128][65];
    __shared__ float ws[8][128];
    int tid = threadIdx.x;
    int b = tid & 63;
    int jl = tid >> 6;
    int j0 = blockIdx.x * 8;
    int j = j0 + jl;

    float acc = 0.f;
    for (int kb = 0; kb < 4; kb++) {
        int kbase = kb * 128;
#pragma unroll
        for (int r = 0; r < 16; r++) {
            int i = tid + r * 512;
            int kk = i & 127, bb2 = i >> 7;
            hs[kk][bb2] = src[bb2 * HH + kbase + kk];
        }
#pragma unroll
        for (int r = 0; r < 2; r++) {
            int i = tid + r * 512;
            int kk = i & 127, rr = i >> 7;
            ws[rr][kk] = W[(size_t)(j0 + rr) * ldw + kbase + kk];
        }
        __syncthreads();
#pragma unroll 8
        for (int k = 0; k < 128; k += 4) {
            float4 wv = *(const float4*)&ws[jl][k];
            acc += hs[k][b] * wv.x + hs[k + 1][b] * wv.y
                 + hs[k + 2][b] * wv.z + hs[k + 3][b] * wv.w;
        }
        __syncthreads();
    }
    if (bias) acc += bias[j];
    if (act) acc = tanhf(acc);
    dst[b * HH + j] = acc;
}

// ---------------- attention ----------------
__global__ __launch_bounds__(256) void attn_kernel(
    const float* __restrict__ W_a2, const float* __restrict__ b_a2)
{
    __shared__ float qs[HH];
    __shared__ float was[HH];
    __shared__ float ss[TX];
    __shared__ float wgt[TX];

    int b = blockIdx.x;
    int tid = threadIdx.x;
    int lane = tid & 31;
    int warp = tid >> 5;

    for (int i = tid; i < HH; i += 256) {
        qs[i] = g_q[b * HH + i];
        was[i] = W_a2[i];
    }
    __syncthreads();

    for (int tt = 0; tt < 8; tt++) {
        int t = warp * 8 + tt;
        const float* Prow = g_P + (size_t)(t * BB + b) * HH;
        float p = 0.f;
#pragma unroll 4
        for (int jj = lane; jj < HH; jj += 32)
            p += was[jj] * tanhf(qs[jj] + Prow[jj]);
#pragma unroll
        for (int o = 16; o > 0; o >>= 1)
            p += __shfl_down_sync(0xffffffffu, p, o);
        if (lane == 0) ss[t] = p + b_a2[0];
    }
    __syncthreads();

    if (tid < 32) {
        float v0 = ss[tid], v1 = ss[tid + 32];
        float m = fmaxf(v0, v1);
#pragma unroll
        for (int o = 16; o > 0; o >>= 1)
            m = fmaxf(m, __shfl_xor_sync(0xffffffffu, m, o));
        float e0 = expf(v0 - m), e1 = expf(v1 - m);
        float s = e0 + e1;
#pragma unroll
        for (int o = 16; o > 0; o >>= 1)
            s += __shfl_xor_sync(0xffffffffu, s, o);
        wgt[tid] = e0 / s;
        wgt[tid + 32] = e1 / s;
    }
    __syncthreads();

    for (int i = tid; i < CTXD; i += 256) {
        float c = 0.f;
#pragma unroll 8
        for (int t = 0; t < TX; t++)
            c += wgt[t] * g_enc[(size_t)(t * BB + b) * CTXD + i];
        g_lin[b * H3 + HH + i] = c;
        g_rnnin[b * RNNIN + EE + i] = c;
    }
}

// ---------------- embedding lookup ----------------
__global__ void embed_kernel(const float* __restrict__ dec_emb)
{
    int b = blockIdx.x;
    int tok = g_tok[b];
    for (int i = threadIdx.x; i < EE; i += blockDim.x)
        g_rnnin[b * RNNIN + i] = dec_emb[(size_t)tok * EE + i];
}

// ---------------- decoder GRU ----------------
__global__ __launch_bounds__(256) void decgru_kernel(
    int s,
    const float* __restrict__ Wih, const float* __restrict__ Whh,
    const float* __restrict__ bih, const float* __restrict__ bhh)
{
    __shared__ float xs[128][65];
    __shared__ float ws[12][128];

    int tid = threadIdx.x;
    int b = tid & 63;
    int jl = tid >> 6;
    int j0 = blockIdx.x * 4;
    int j = j0 + jl;
    int par = s & 1;
    const float* hin = g_hd[par];
    float* hout = g_hd[par ^ 1];

    float ar = 0.f, az = 0.f, anx = 0.f, anh = 0.f;

    for (int kb = 0; kb < 10; kb++) {
        int kbase = kb * 128;
#pragma unroll
        for (int r = 0; r < 32; r++) {
            int i = tid + r * 256;
            int kk = i & 127, bb2 = i >> 7;
            xs[kk][bb2] = g_rnnin[bb2 * RNNIN + kbase + kk];
        }
#pragma unroll
        for (int r = 0; r < 6; r++) {
            int i = tid + r * 256;
            int kk = i & 127, rr = i >> 7;
            int g = rr >> 2, jloc = rr & 3;
            ws[rr][kk] = Wih[(size_t)(g * HH + j0 + jloc) * RNNIN + kbase + kk];
        }
        __syncthreads();
#pragma unroll 8
        for (int k = 0; k < 128; k += 4) {
            float4 wr = *(const float4*)&ws[jl][k];
            float4 wz = *(const float4*)&ws[4 + jl][k];
            float4 wn = *(const float4*)&ws[8 + jl][k];
            float x0 = xs[k][b], x1 = xs[k + 1][b], x2 = xs[k + 2][b], x3 = xs[k + 3][b];
            ar += x0 * wr.x + x1 * wr.y + x2 * wr.z + x3 * wr.w;
            az += x0 * wz.x + x1 * wz.y + x2 * wz.z + x3 * wz.w;
            anx += x0 * wn.x + x1 * wn.y + x2 * wn.z + x3 * wn.w;
        }
        __syncthreads();
    }

    for (int kb = 0; kb < 4; kb++) {
        int kbase = kb * 128;
#pragma unroll
        for (int r = 0; r < 32; r++) {
            int i = tid + r * 256;
            int kk = i & 127, bb2 = i >> 7;
            xs[kk][bb2] = hin[bb2 * HH + kbase + kk];
        }
#pragma unroll
        for (int r = 0; r < 6; r++) {
            int i = tid + r * 256;
            int kk = i & 127, rr = i >> 7;
            int g = rr >> 2, jloc = rr & 3;
            ws[rr][kk] = Whh[(size_t)(g * HH + j0 + jloc) * HH + kbase + kk];
        }
        __syncthreads();
#pragma unroll 8
        for (int k = 0; k < 128; k += 4) {
            float4 wr = *(const float4*)&ws[jl][k];
            float4 wz = *(const float4*)&ws[4 + jl][k];
            float4 wn = *(const float4*)&ws[8 + jl][k];
            float x0 = xs[k][b], x1 = xs[k + 1][b], x2 = xs[k + 2][b], x3 = xs[k + 3][b];
            ar += x0 * wr.x + x1 * wr.y + x2 * wr.z + x3 * wr.w;
            az += x0 * wz.x + x1 * wz.y + x2 * wz.z + x3 * wz.w;
            anh += x0 * wn.x + x1 * wn.y + x2 * wn.z + x3 * wn.w;
        }
        __syncthreads();
    }

    float r = sigm(ar + bih[j] + bhh[j]);
    float z = sigm(az + bih[HH + j] + bhh[HH + j]);
    float n = tanhf(anx + bih[2 * HH + j] + r * (anh + bhh[2 * HH + j]));
    float hold = hin[b * HH + j];
    float h2 = (1.f - z) * n + z * hold;
    hout[b * HH + j] = h2;
    g_lin[b * H3 + j] = h2;
}

// ---------------- log-softmax + argmax ----------------
__global__ __launch_bounds__(256) void lsm_kernel(float* __restrict__ out, int step)
{
    __shared__ float rm[256];
    __shared__ int ri[256];
    __shared__ float rs[256];

    int b = blockIdx.x;
    int tid = threadIdx.x;
    float* row = out + (size_t)(step * BB + b) * KY;

    float m = -1e30f; int mi = 0;
    for (int i = tid; i < KY; i += 256) {
        float v = row[i];
        if (v > m) { m = v; mi = i; }
    }
    rm[tid] = m; ri[tid] = mi;
    __syncthreads();
    for (int o = 128; o > 0; o >>= 1) {
        if (tid < o) {
            float vb = rm[tid + o]; int ib = ri[tid + o];
            if (vb > rm[tid] || (vb == rm[tid] && ib < ri[tid])) { rm[tid] = vb; ri[tid] = ib; }
        }
        __syncthreads();
    }
    float M = rm[0];
    int Mi = ri[0];

    float s = 0.f;
    for (int i = tid; i < KY; i += 256) s += expf(row[i] - M);
    rs[tid] = s;
    __syncthreads();
    for (int o = 128; o > 0; o >>= 1) {
        if (tid < o) rs[tid] += rs[tid + o];
        __syncthreads();
    }
    float lse = M + logf(rs[0]);

    for (int i = tid; i < KY; i += 256) row[i] = row[i] - lse;
    if (tid == 0) g_tok[b] = Mi;
}

// ---------------- host launch ----------------
extern "C" void kernel_launch(void* const* d_in, const int* in_sizes, int n_in,
                              void* d_out, int out_size)
{
    const int*   inputs  = (const int*)d_in[0];
    const float* enc_emb = (const float*)d_in[2];
    const float* W_ih_f  = (const float*)d_in[3];
    const float* W_hh_f  = (const float*)d_in[4];
    const float* b_ih_f  = (const float*)d_in[5];
    const float* b_hh_f  = (const float*)d_in[6];
    const float* W_ih_b  = (const float*)d_in[7];
    const float* W_hh_b  = (const float*)d_in[8];
    const float* b_ih_b  = (const float*)d_in[9];
    const float* b_hh_b  = (const float*)d_in[10];
    const float* W_init  = (const float*)d_in[11];
    const float* b_init  = (const float*)d_in[12];
    const float* dec_emb = (const float*)d_in[13];
    const float* W_ih_d  = (const float*)d_in[14];
    const float* W_hh_d  = (const float*)d_in[15];
    const float* b_ih_d  = (const float*)d_in[16];
    const float* b_hh_d  = (const float*)d_in[17];
    const float* W_lsm   = (const float*)d_in[18];
    const float* b_lsm   = (const float*)d_in[19];
    const float* W_a1    = (const float*)d_in[20];
    const float* b_a1    = (const float*)d_in[21];
    const float* W_a2    = (const float*)d_in[22];
    const float* b_a2    = (const float*)d_in[23];
    float* out = (float*)d_out;

    static float* p_P    = nullptr;
    static float* p_gi_f = nullptr;
    static float* p_gi_b = nullptr;
    static float* p_enc  = nullptr;
    static float* p_lin  = nullptr;
    static float* p_hd   = nullptr;
    static float* p_henc = nullptr;
    static float* p_q    = nullptr;
    static bool attr_done = false;
    if (!p_gi_f) {
        cudaGetSymbolAddress((void**)&p_gi_f, g_gi_f);
        cudaGetSymbolAddress((void**)&p_gi_b, g_gi_b);
        cudaGetSymbolAddress((void**)&p_enc,  g_enc);
        cudaGetSymbolAddress((void**)&p_P,    g_P);
        cudaGetSymbolAddress((void**)&p_lin,  g_lin);
        cudaGetSymbolAddress((void**)&p_hd,   g_hd);
        cudaGetSymbolAddress((void**)&p_henc, g_henc);
        cudaGetSymbolAddress((void**)&p_q,    g_q);
    }
    if (!attr_done) {
        cudaFuncSetAttribute(logits_mma_kernel,
                             cudaFuncAttributeMaxDynamicSharedMemorySize, LG_SMEM_TOTAL);
        attr_done = true;
    }

    init_kernel<<<128, 256>>>();

    // W_lsm -> bf16 hi/lo split (once per launch)
    convw_kernel<<<(int)(((size_t)KY * H3 / 4) / 256), 256>>>(W_lsm);

    // batched input-side GRU preactivations
    sgemm_kernel<<<dim3(H3 / 128, TX * BB / 64), 256>>>(
        enc_emb, inputs, W_ih_f, EE, b_ih_f, p_gi_f, H3, EE);
    sgemm_kernel<<<dim3(H3 / 128, TX * BB / 64), 256>>>(
        enc_emb, inputs, W_ih_b, EE, b_ih_b, p_gi_b, H3, EE);

    // encoder recurrence
    for (int t = 0; t < TX; t++)
        enc_step_kernel<<<dim3(64, 2), 512>>>(t, W_hh_f, b_hh_f, W_hh_b, b_hh_b);

    // step-invariant attention term
    sgemm_kernel<<<dim3(HH / 128, TX * BB / 64), 256>>>(
        p_enc, nullptr, W_a1 + HH, H3, b_a1, p_P, HH, CTXD);

    // decoder hidden init
    colproj_kernel<<<64, 512>>>(p_henc + 2 * BB * HH, W_init, HH, b_init, p_hd, 1);

    for (int s = 0; s < TY; s++) {
        float* hcur = p_hd + (s & 1) * BB * HH;
        colproj_kernel<<<64, 512>>>(hcur, W_a1, H3, nullptr, p_q, 0);
        embed_kernel<<<64, 256>>>(dec_emb);
        attn_kernel<<<64, 256>>>(W_a2, b_a2);
        decgru_kernel<<<128, 256>>>(s, W_ih_d, W_hh_d, b_ih_d, b_hh_d);
        conva_kernel<<<(BB * H3 / 4) / 256, 256>>>();
        logits_mma_kernel<<<KY / 256, 256, LG_SMEM_TOTAL>>>(b_lsm, out, s);
        lsm_kernel<<<64, 256>>>(out, s);
    }
}

// round 4
// speedup vs baseline: 2.0888x; 1.0878x over previous
#include <cuda_runtime.h>
#include <cuda_bf16.h>
#include <math.h>
#include <stdint.h>

// Problem constants
#define TX 64
#define BB 64
#define TY 32
#define EE 256
#define HH 512
#define H3 1536
#define KY 32000
#define CTXD 1024      // 2H
#define RNNIN 1280     // E + 2H
#define NTILE (KY / 256)   // 125 vocab tiles

// ---------------- device scratch (static globals; no allocation) ----------------
__device__ float g_gi_f[TX * BB * H3];
__device__ float g_gi_b[TX * BB * H3];
__device__ float g_henc[2][2][BB * HH];
__device__ float g_enc[TX * BB * CTXD];
__device__ float g_P[TX * BB * HH];
__device__ float g_hd[2][BB * HH];
__device__ float g_q[BB * HH];
__device__ float g_rnnin[BB * RNNIN];
__device__ int   g_tok[BB];

// bf16 split copies for tensor-core logits GEMM
__device__ __nv_bfloat16 g_wh[(size_t)KY * H3];   // hi(W_lsm)
__device__ __nv_bfloat16 g_wl[(size_t)KY * H3];   // lo(W_lsm)
__device__ __nv_bfloat16 g_ah[BB * H3];           // hi of [h2, context]
__device__ __nv_bfloat16 g_al[BB * H3];           // lo of [h2, context]

// per-tile softmax partials (from logits epilogue)
__device__ float g_pm[NTILE][BB];
__device__ int   g_pa[NTILE][BB];
__device__ float g_ps[NTILE][BB];

// encoder software barrier state
__device__ volatile unsigned g_bar_gen[2];
__device__ unsigned g_bar_cnt[2];

__device__ __forceinline__ float sigm(float x) { return 1.0f / (1.0f + expf(-x)); }

__device__ __forceinline__ void split_store(float v, __nv_bfloat16* ph, __nv_bfloat16* pl)
{
    __nv_bfloat16 h = __float2bfloat16(v);
    *ph = h;
    *pl = __float2bfloat16(v - __bfloat162float(h));
}

// ---------------- init ----------------
__global__ void init_kernel() {
    int i = blockIdx.x * blockDim.x + threadIdx.x;
    if (i < BB * HH) {
        g_henc[0][0][i] = 0.f;
        g_henc[1][0][i] = 0.f;
    }
    if (i < BB) g_tok[i] = 1;
    if (i < 2) { g_bar_gen[i] = 0; g_bar_cnt[i] = 0; }
}

// ---------------- W_lsm -> bf16 hi/lo split (once per launch) ----------------
__global__ __launch_bounds__(256) void convw_kernel(const float* __restrict__ W) {
    size_t i = (size_t)blockIdx.x * blockDim.x + threadIdx.x;  // over KY*H3/4
    const float4* W4 = (const float4*)W;
    float4 v = W4[i];
    __nv_bfloat16 h0 = __float2bfloat16(v.x);
    __nv_bfloat16 h1 = __float2bfloat16(v.y);
    __nv_bfloat16 h2 = __float2bfloat16(v.z);
    __nv_bfloat16 h3 = __float2bfloat16(v.w);
    __nv_bfloat16 l0 = __float2bfloat16(v.x - __bfloat162float(h0));
    __nv_bfloat16 l1 = __float2bfloat16(v.y - __bfloat162float(h1));
    __nv_bfloat16 l2 = __float2bfloat16(v.z - __bfloat162float(h2));
    __nv_bfloat16 l3 = __float2bfloat16(v.w - __bfloat162float(h3));
    __nv_bfloat162* H2 = reinterpret_cast<__nv_bfloat162*>(g_wh);
    __nv_bfloat162* L2 = reinterpret_cast<__nv_bfloat162*>(g_wl);
    H2[2 * i]     = __nv_bfloat162{h0, h1};
    H2[2 * i + 1] = __nv_bfloat162{h2, h3};
    L2[2 * i]     = __nv_bfloat162{l0, l1};
    L2[2 * i + 1] = __nv_bfloat162{l2, l3};
}

// ---------------- mma.sync bf16 helper ----------------
__device__ __forceinline__ void mma16816(float* d, const uint32_t* a, uint32_t b0, uint32_t b1)
{
    asm volatile(
        "mma.sync.aligned.m16n8k16.row.col.f32.bf16.bf16.f32 "
        "{%0,%1,%2,%3}, {%4,%5,%6,%7}, {%8,%9}, {%0,%1,%2,%3};"
        : "+f"(d[0]), "+f"(d[1]), "+f"(d[2]), "+f"(d[3])
        : "r"(a[0]), "r"(a[1]), "r"(a[2]), "r"(a[3]), "r"(b0), "r"(b1));
}

// ---------------- logits GEMM via mma.sync (split bf16, fp32 accum) ----------------
#define LG_KC 64
#define LG_ROWB 144
#define LG_W_BYTES (256 * LG_ROWB)
#define LG_A_BYTES (64 * LG_ROWB)
#define LG_STAGE (2 * LG_W_BYTES + 2 * LG_A_BYTES)   // 92160
#define LG_SMEM_TOTAL (2 * LG_STAGE)                 // 184320

__global__ __launch_bounds__(256, 1) void logits_mma_kernel(
    const float* __restrict__ b_lsm, float* __restrict__ out, int step)
{
    extern __shared__ char smem[];
    int tid = threadIdx.x;
    int wid = tid >> 5, lane = tid & 31;
    int vb = blockIdx.x * 256;

    auto load_chunk = [&](int kc, int buf) {
        char* base = smem + buf * LG_STAGE;
        {
            char* dsth = base;
            char* dstl = base + LG_W_BYTES;
            const __nv_bfloat16* sh = g_wh + (size_t)vb * H3 + kc * LG_KC;
            const __nv_bfloat16* sl = g_wl + (size_t)vb * H3 + kc * LG_KC;
#pragma unroll
            for (int it = 0; it < 8; it++) {
                int idx = tid + it * 256;
                int r = idx >> 3, c = idx & 7;
                size_t gofs = (size_t)r * H3 + c * 8;
                uint32_t so = (uint32_t)(r * LG_ROWB + c * 16);
                uint32_t d1 = (uint32_t)__cvta_generic_to_shared(dsth + so);
                uint32_t d2 = (uint32_t)__cvta_generic_to_shared(dstl + so);
                asm volatile("cp.async.cg.shared.global [%0], [%1], 16;" :: "r"(d1), "l"(sh + gofs));
                asm volatile("cp.async.cg.shared.global [%0], [%1], 16;" :: "r"(d2), "l"(sl + gofs));
            }
        }
        {
            char* dsth = base + 2 * LG_W_BYTES;
            char* dstl = dsth + LG_A_BYTES;
            const __nv_bfloat16* sh = g_ah + kc * LG_KC;
            const __nv_bfloat16* sl = g_al + kc * LG_KC;
#pragma unroll
            for (int it = 0; it < 2; it++) {
                int idx = tid + it * 256;
                int r = idx >> 3, c = idx & 7;
                size_t gofs = (size_t)r * H3 + c * 8;
                uint32_t so = (uint32_t)(r * LG_ROWB + c * 16);
                uint32_t d1 = (uint32_t)__cvta_generic_to_shared(dsth + so);
                uint32_t d2 = (uint32_t)__cvta_generic_to_shared(dstl + so);
                asm volatile("cp.async.cg.shared.global [%0], [%1], 16;" :: "r"(d1), "l"(sh + gofs));
                asm volatile("cp.async.cg.shared.global [%0], [%1], 16;" :: "r"(d2), "l"(sl + gofs));
            }
        }
        asm volatile("cp.async.commit_group;" ::: "memory");
    };

    float acc[2][8][4];
#pragma unroll
    for (int mt = 0; mt < 2; mt++)
#pragma unroll
        for (int nt = 0; nt < 8; nt++)
#pragma unroll
            for (int i = 0; i < 4; i++) acc[mt][nt][i] = 0.f;

    int m0 = wid * 32;
    int krow = lane >> 2;
    int kcol4 = (lane & 3) * 4;

    load_chunk(0, 0);

    for (int c = 0; c < H3 / LG_KC; c++) {
        if (c + 1 < H3 / LG_KC) {
            load_chunk(c + 1, (c + 1) & 1);
            asm volatile("cp.async.wait_group 1;" ::: "memory");
        } else {
            asm volatile("cp.async.wait_group 0;" ::: "memory");
        }
        __syncthreads();

        char* base = smem + (c & 1) * LG_STAGE;
        const char* wh = base;
        const char* wl = base + LG_W_BYTES;
        const char* ab_h = base + 2 * LG_W_BYTES;
        const char* ab_l = ab_h + LG_A_BYTES;

#pragma unroll
        for (int kt = 0; kt < 4; kt++) {
            int kb = kt * 32 + kcol4;
            uint32_t ah[2][4], al[2][4];
#pragma unroll
            for (int mt = 0; mt < 2; mt++) {
                int ro = (m0 + mt * 16 + krow) * LG_ROWB + kb;
                ah[mt][0] = *(const uint32_t*)(wh + ro);
                ah[mt][1] = *(const uint32_t*)(wh + ro + 8 * LG_ROWB);
                ah[mt][2] = *(const uint32_t*)(wh + ro + 16);
                ah[mt][3] = *(const uint32_t*)(wh + ro + 8 * LG_ROWB + 16);
                al[mt][0] = *(const uint32_t*)(wl + ro);
                al[mt][1] = *(const uint32_t*)(wl + ro + 8 * LG_ROWB);
                al[mt][2] = *(const uint32_t*)(wl + ro + 16);
                al[mt][3] = *(const uint32_t*)(wl + ro + 8 * LG_ROWB + 16);
            }
#pragma unroll
            for (int nt = 0; nt < 8; nt++) {
                int ro = (nt * 8 + krow) * LG_ROWB + kb;
                uint32_t bh0 = *(const uint32_t*)(ab_h + ro);
                uint32_t bh1 = *(const uint32_t*)(ab_h + ro + 16);
                uint32_t bl0 = *(const uint32_t*)(ab_l + ro);
                uint32_t bl1 = *(const uint32_t*)(ab_l + ro + 16);
#pragma unroll
                for (int mt = 0; mt < 2; mt++) {
                    mma16816(acc[mt][nt], ah[mt], bh0, bh1);
                    mma16816(acc[mt][nt], ah[mt], bl0, bl1);
                    mma16816(acc[mt][nt], al[mt], bh0, bh1);
                }
            }
        }
        __syncthreads();
    }

    // ---- epilogue: bias + store + per-tile softmax partials ----
    float* obase = out + (size_t)step * BB * KY;
#pragma unroll
    for (int mt = 0; mt < 2; mt++) {
#pragma unroll
        for (int h = 0; h < 2; h++) {
            int v = vb + m0 + mt * 16 + krow + h * 8;
            float bias = b_lsm[v];
#pragma unroll
            for (int nt = 0; nt < 8; nt++) {
                int b0 = nt * 8 + (lane & 3) * 2;
                acc[mt][nt][h * 2 + 0] += bias;
                acc[mt][nt][h * 2 + 1] += bias;
                obase[(size_t)b0 * KY + v]       = acc[mt][nt][h * 2 + 0];
                obase[(size_t)(b0 + 1) * KY + v] = acc[mt][nt][h * 2 + 1];
            }
        }
    }
    __syncthreads();  // pipeline buffers no longer needed; reuse smem

    float* smf  = (float*)smem;            // [8][64]
    int*   smi  = (int*)(smem + 2048);     // [8][64]
    float* tmx  = (float*)(smem + 4096);   // [64]
    int*   targ = (int*)(smem + 4352);     // [64]

    int vbase = vb + m0 + krow;
    // phase 1: max + argmax
#pragma unroll
    for (int nt = 0; nt < 8; nt++) {
#pragma unroll
        for (int c = 0; c < 2; c++) {
            int bcol = nt * 8 + (lane & 3) * 2 + c;
            float mv = acc[0][nt][c];     int mi = vbase;
            float v2 = acc[0][nt][2 + c];
            if (v2 > mv) { mv = v2; mi = vbase + 8; }
            v2 = acc[1][nt][c];
            if (v2 > mv) { mv = v2; mi = vbase + 16; }
            v2 = acc[1][nt][2 + c];
            if (v2 > mv) { mv = v2; mi = vbase + 24; }
#pragma unroll
            for (int o = 4; o <= 16; o <<= 1) {
                float ov = __shfl_xor_sync(0xffffffffu, mv, o);
                int oi = __shfl_xor_sync(0xffffffffu, mi, o);
                if (ov > mv || (ov == mv && oi < mi)) { mv = ov; mi = oi; }
            }
            if ((lane >> 2) == 0) { smf[wid * 64 + bcol] = mv; smi[wid * 64 + bcol] = mi; }
        }
    }
    __syncthreads();
    if (tid < 64) {
        float mv = smf[tid]; int mi = smi[tid];
#pragma unroll
        for (int w = 1; w < 8; w++) {
            float ov = smf[w * 64 + tid]; int oi = smi[w * 64 + tid];
            if (ov > mv || (ov == mv && oi < mi)) { mv = ov; mi = oi; }
        }
        tmx[tid] = mv; targ[tid] = mi;
    }
    __syncthreads();
    // phase 2: sum of exp(x - tile_max)
#pragma unroll
    for (int nt = 0; nt < 8; nt++) {
#pragma unroll
        for (int c = 0; c < 2; c++) {
            int bcol = nt * 8 + (lane & 3) * 2 + c;
            float tm = tmx[bcol];
            float s = expf(acc[0][nt][c] - tm) + expf(acc[0][nt][2 + c] - tm)
                    + expf(acc[1][nt][c] - tm) + expf(acc[1][nt][2 + c] - tm);
#pragma unroll
            for (int o = 4; o <= 16; o <<= 1)
                s += __shfl_xor_sync(0xffffffffu, s, o);
            if ((lane >> 2) == 0) smf[wid * 64 + bcol] = s;
        }
    }
    __syncthreads();
    if (tid < 64) {
        float s = 0.f;
#pragma unroll
        for (int w = 0; w < 8; w++) s += smf[w * 64 + tid];
        g_pm[blockIdx.x][tid] = tmx[tid];
        g_pa[blockIdx.x][tid] = targ[tid];
        g_ps[blockIdx.x][tid] = s;
    }
}

// ---------------- generic SGEMM: C[M,N] = A@W^T + bias ----------------
__global__ __launch_bounds__(256) void sgemm_kernel(
    const float* __restrict__ A, const int* __restrict__ gather,
    const float* __restrict__ W, int ldw,
    const float* __restrict__ bias,
    float* __restrict__ C, int N, int K)
{
    __shared__ float As[16][64];
    __shared__ float Ws[16][128];
    int tid = threadIdx.x;
    int m0 = blockIdx.y * 64;
    int n0 = blockIdx.x * 128;
    int tx = tid & 15, ty = tid >> 4;

    float acc[4][8];
#pragma unroll
    for (int i = 0; i < 4; i++)
#pragma unroll
        for (int j = 0; j < 8; j++) acc[i][j] = 0.f;

    int lrow = tid >> 2;
    int lk = (tid & 3) * 4;
    int arow = m0 + lrow;
    int aphys = gather ? gather[arow] : arow;
    const float* Aptr = A + (size_t)aphys * K + lk;

    for (int k0 = 0; k0 < K; k0 += 16) {
        float4 av = *(const float4*)(Aptr + k0);
        As[lk + 0][lrow] = av.x; As[lk + 1][lrow] = av.y;
        As[lk + 2][lrow] = av.z; As[lk + 3][lrow] = av.w;
#pragma unroll
        for (int r = 0; r < 2; r++) {
            int nrow = lrow + r * 64;
            float4 wv = *(const float4*)(W + (size_t)(n0 + nrow) * ldw + k0 + lk);
            Ws[lk + 0][nrow] = wv.x; Ws[lk + 1][nrow] = wv.y;
            Ws[lk + 2][nrow] = wv.z; Ws[lk + 3][nrow] = wv.w;
        }
        __syncthreads();
#pragma unroll
        for (int kk = 0; kk < 16; kk++) {
            float a[4];
#pragma unroll
            for (int i = 0; i < 4; i++) a[i] = As[kk][ty * 4 + i];
            float4 b0 = *(const float4*)&Ws[kk][tx * 8];
            float4 b1 = *(const float4*)&Ws[kk][tx * 8 + 4];
            float bb8[8] = { b0.x, b0.y, b0.z, b0.w, b1.x, b1.y, b1.z, b1.w };
#pragma unroll
            for (int i = 0; i < 4; i++)
#pragma unroll
                for (int j = 0; j < 8; j++) acc[i][j] += a[i] * bb8[j];
        }
        __syncthreads();
    }
#pragma unroll
    for (int i = 0; i < 4; i++) {
        int m = m0 + ty * 4 + i;
        float* crow = C + (size_t)m * N + n0 + tx * 8;
#pragma unroll
        for (int j = 0; j < 8; j++) {
            float v = acc[i][j];
            if (bias) v += bias[n0 + tx * 8 + j];
            crow[j] = v;
        }
    }
}

// ---------------- persistent encoder: all 64 timesteps, both dirs, one launch ----------------
// grid (64 j-tiles, 2 dirs) = 128 CTAs (all resident), 512 threads.
// Whh slice persists in smem; per-dir software barrier between timesteps.
// Hidden-state global traffic uses __ldcg/__stcg (L1 bypass — cross-SM recurrence).
#define ENC_WS_FLOATS (24 * 512)
#define ENC_SMEM ((ENC_WS_FLOATS + 128 * 65) * 4)

__device__ __forceinline__ void dir_barrier(int dir, int tid)
{
    __threadfence();
    __syncthreads();
    if (tid == 0) {
        unsigned gen = g_bar_gen[dir];
        unsigned t = atomicAdd(&g_bar_cnt[dir], 1u);
        if (t == 63u) {
            g_bar_cnt[dir] = 0u;
            __threadfence();
            g_bar_gen[dir] = gen + 1u;
        } else {
            while (g_bar_gen[dir] == gen) __nanosleep(40);
        }
    }
    __syncthreads();
}

__global__ __launch_bounds__(512, 1) void enc_persist_kernel(
    const float* __restrict__ Whh_f, const float* __restrict__ bhh_f,
    const float* __restrict__ Whh_b, const float* __restrict__ bhh_b)
{
    extern __shared__ float sm[];
    float* ws = sm;                                   // [24][512]
    float (*hs)[65] = (float(*)[65])(sm + ENC_WS_FLOATS);  // [128][65]

    int dir = blockIdx.y;
    const float* Whh = dir ? Whh_b : Whh_f;
    const float* bhh = dir ? bhh_b : bhh_f;
    int tid = threadIdx.x;
    int b = tid & 63;
    int jl = tid >> 6;          // 0..7
    int j0 = blockIdx.x * 8;
    int j = j0 + jl;
    int colofs = dir ? HH : 0;

    // persist weights: row rr -> gate g=rr>>3, jloc=rr&7
    for (int idx = tid; idx < ENC_WS_FLOATS; idx += 512) {
        int rr = idx >> 9, kk = idx & 511;
        ws[idx] = Whh[(size_t)((rr >> 3) * HH + j0 + (rr & 7)) * HH + kk];
    }
    float br = bhh[j], bz = bhh[HH + j], bn = bhh[2 * HH + j];
    __syncthreads();

    for (int t = 0; t < TX; t++) {
        int par = t & 1;
        int row = dir ? (TX - 1 - t) : t;
        const float* gi = (dir ? g_gi_b : g_gi_f) + (size_t)row * BB * H3;
        const float* hin = g_henc[dir][par];
        float* hout = g_henc[dir][par ^ 1];

        float dr = 0.f, dz = 0.f, dn = 0.f;
        for (int kb = 0; kb < 4; kb++) {
            int kbase = kb * 128;
#pragma unroll
            for (int r = 0; r < 16; r++) {
                int i = tid + r * 512;
                int kk = i & 127, bb2 = i >> 7;
                hs[kk][bb2] = __ldcg(&hin[bb2 * HH + kbase + kk]);
            }
            __syncthreads();
            const float* wr4 = ws + jl * 512 + kbase;
            const float* wz4 = ws + (8 + jl) * 512 + kbase;
            const float* wn4 = ws + (16 + jl) * 512 + kbase;
#pragma unroll 8
            for (int k = 0; k < 128; k += 4) {
                float4 wr = *(const float4*)(wr4 + k);
                float4 wz = *(const float4*)(wz4 + k);
                float4 wn = *(const float4*)(wn4 + k);
                float h0 = hs[k][b], h1 = hs[k + 1][b], h2v = hs[k + 2][b], h3v = hs[k + 3][b];
                dr += h0 * wr.x + h1 * wr.y + h2v * wr.z + h3v * wr.w;
                dz += h0 * wz.x + h1 * wz.y + h2v * wz.z + h3v * wz.w;
                dn += h0 * wn.x + h1 * wn.y + h2v * wn.z + h3v * wn.w;
            }
            __syncthreads();
        }

        const float* girow = gi + b * H3;
        float r = sigm(girow[j] + dr + br);
        float z = sigm(girow[HH + j] + dz + bz);
        float n = tanhf(girow[2 * HH + j] + r * (dn + bn));
        float hold = __ldcg(&hin[b * HH + j]);
        float h2 = (1.f - z) * n + z * hold;
        __stcg(&hout[b * HH + j], h2);
        g_enc[(size_t)(row * BB + b) * CTXD + colofs + j] = h2;

        if (t + 1 < TX) dir_barrier(dir, tid);
    }
}

// ---------------- column projection ----------------
__global__ __launch_bounds__(512) void colproj_kernel(
    const float* __restrict__ src, const float* __restrict__ W, int ldw,
    const float* __restrict__ bias, float* __restrict__ dst, int act)
{
    __shared__ float hs[128][65];
    __shared__ float ws[8][128];
    int tid = threadIdx.x;
    int b = tid & 63;
    int jl = tid >> 6;
    int j0 = blockIdx.x * 8;
    int j = j0 + jl;

    float acc = 0.f;
    for (int kb = 0; kb < 4; kb++) {
        int kbase = kb * 128;
#pragma unroll
        for (int r = 0; r < 16; r++) {
            int i = tid + r * 512;
            int kk = i & 127, bb2 = i >> 7;
            hs[kk][bb2] = src[bb2 * HH + kbase + kk];
        }
#pragma unroll
        for (int r = 0; r < 2; r++) {
            int i = tid + r * 512;
            int kk = i & 127, rr = i >> 7;
            ws[rr][kk] = W[(size_t)(j0 + rr) * ldw + kbase + kk];
        }
        __syncthreads();
#pragma unroll 8
        for (int k = 0; k < 128; k += 4) {
            float4 wv = *(const float4*)&ws[jl][k];
            acc += hs[k][b] * wv.x + hs[k + 1][b] * wv.y
                 + hs[k + 2][b] * wv.z + hs[k + 3][b] * wv.w;
        }
        __syncthreads();
    }
    if (bias) acc += bias[j];
    if (act) acc = tanhf(acc);
    dst[b * HH + j] = acc;
}

// ---------------- attention + embedding (fused) ----------------
__global__ __launch_bounds__(256) void attn_kernel(
    const float* __restrict__ W_a2, const float* __restrict__ b_a2,
    const float* __restrict__ dec_emb)
{
    __shared__ float qs[HH];
    __shared__ float was[HH];
    __shared__ float ss[TX];
    __shared__ float wgt[TX];

    int b = blockIdx.x;
    int tid = threadIdx.x;
    int lane = tid & 31;
    int warp = tid >> 5;

    // embedding lookup for this step's input token (written by previous lsm)
    int tok = g_tok[b];
    for (int i = tid; i < EE; i += 256)
        g_rnnin[b * RNNIN + i] = dec_emb[(size_t)tok * EE + i];

    for (int i = tid; i < HH; i += 256) {
        qs[i] = g_q[b * HH + i];
        was[i] = W_a2[i];
    }
    __syncthreads();

    for (int tt = 0; tt < 8; tt++) {
        int t = warp * 8 + tt;
        const float* Prow = g_P + (size_t)(t * BB + b) * HH;
        float p = 0.f;
#pragma unroll 4
        for (int jj = lane; jj < HH; jj += 32)
            p += was[jj] * tanhf(qs[jj] + Prow[jj]);
#pragma unroll
        for (int o = 16; o > 0; o >>= 1)
            p += __shfl_down_sync(0xffffffffu, p, o);
        if (lane == 0) ss[t] = p + b_a2[0];
    }
    __syncthreads();

    if (tid < 32) {
        float v0 = ss[tid], v1 = ss[tid + 32];
        float m = fmaxf(v0, v1);
#pragma unroll
        for (int o = 16; o > 0; o >>= 1)
            m = fmaxf(m, __shfl_xor_sync(0xffffffffu, m, o));
        float e0 = expf(v0 - m), e1 = expf(v1 - m);
        float s = e0 + e1;
#pragma unroll
        for (int o = 16; o > 0; o >>= 1)
            s += __shfl_xor_sync(0xffffffffu, s, o);
        wgt[tid] = e0 / s;
        wgt[tid + 32] = e1 / s;
    }
    __syncthreads();

    for (int i = tid; i < CTXD; i += 256) {
        float c = 0.f;
#pragma unroll 8
        for (int t = 0; t < TX; t++)
            c += wgt[t] * g_enc[(size_t)(t * BB + b) * CTXD + i];
        g_rnnin[b * RNNIN + EE + i] = c;
        split_store(c, &g_ah[b * H3 + HH + i], &g_al[b * H3 + HH + i]);
    }
}

// ---------------- decoder GRU (fused input+hidden GEMM + gates + bf16 split out) ----------------
__global__ __launch_bounds__(256) void decgru_kernel(
    int s,
    const float* __restrict__ Wih, const float* __restrict__ Whh,
    const float* __restrict__ bih, const float* __restrict__ bhh)
{
    __shared__ float xs[128][65];
    __shared__ float ws[12][128];

    int tid = threadIdx.x;
    int b = tid & 63;
    int jl = tid >> 6;
    int j0 = blockIdx.x * 4;
    int j = j0 + jl;
    int par = s & 1;
    const float* hin = g_hd[par];
    float* hout = g_hd[par ^ 1];

    float ar = 0.f, az = 0.f, anx = 0.f, anh = 0.f;

    for (int kb = 0; kb < 10; kb++) {
        int kbase = kb * 128;
#pragma unroll
        for (int r = 0; r < 32; r++) {
            int i = tid + r * 256;
            int kk = i & 127, bb2 = i >> 7;
            xs[kk][bb2] = g_rnnin[bb2 * RNNIN + kbase + kk];
        }
#pragma unroll
        for (int r = 0; r < 6; r++) {
            int i = tid + r * 256;
            int kk = i & 127, rr = i >> 7;
            int g = rr >> 2, jloc = rr & 3;
            ws[rr][kk] = Wih[(size_t)(g * HH + j0 + jloc) * RNNIN + kbase + kk];
        }
        __syncthreads();
#pragma unroll 8
        for (int k = 0; k < 128; k += 4) {
            float4 wr = *(const float4*)&ws[jl][k];
            float4 wz = *(const float4*)&ws[4 + jl][k];
            float4 wn = *(const float4*)&ws[8 + jl][k];
            float x0 = xs[k][b], x1 = xs[k + 1][b], x2 = xs[k + 2][b], x3 = xs[k + 3][b];
            ar += x0 * wr.x + x1 * wr.y + x2 * wr.z + x3 * wr.w;
            az += x0 * wz.x + x1 * wz.y + x2 * wz.z + x3 * wz.w;
            anx += x0 * wn.x + x1 * wn.y + x2 * wn.z + x3 * wn.w;
        }
        __syncthreads();
    }

    for (int kb = 0; kb < 4; kb++) {
        int kbase = kb * 128;
#pragma unroll
        for (int r = 0; r < 32; r++) {
            int i = tid + r * 256;
            int kk = i & 127, bb2 = i >> 7;
            xs[kk][bb2] = hin[bb2 * HH + kbase + kk];
        }
#pragma unroll
        for (int r = 0; r < 6; r++) {
            int i = tid + r * 256;
            int kk = i & 127, rr = i >> 7;
            int g = rr >> 2, jloc = rr & 3;
            ws[rr][kk] = Whh[(size_t)(g * HH + j0 + jloc) * HH + kbase + kk];
        }
        __syncthreads();
#pragma unroll 8
        for (int k = 0; k < 128; k += 4) {
            float4 wr = *(const float4*)&ws[jl][k];
            float4 wz = *(const float4*)&ws[4 + jl][k];
            float4 wn = *(const float4*)&ws[8 + jl][k];
            float x0 = xs[k][b], x1 = xs[k + 1][b], x2 = xs[k + 2][b], x3 = xs[k + 3][b];
            ar += x0 * wr.x + x1 * wr.y + x2 * wr.z + x3 * wr.w;
            az += x0 * wz.x + x1 * wz.y + x2 * wz.z + x3 * wz.w;
            anh += x0 * wn.x + x1 * wn.y + x2 * wn.z + x3 * wn.w;
        }
        __syncthreads();
    }

    float r = sigm(ar + bih[j] + bhh[j]);
    float z = sigm(az + bih[HH + j] + bhh[HH + j]);
    float n = tanhf(anx + bih[2 * HH + j] + r * (anh + bhh[2 * HH + j]));
    float hold = hin[b * HH + j];
    float h2 = (1.f - z) * n + z * hold;
    hout[b * HH + j] = h2;
    split_store(h2, &g_ah[b * H3 + j], &g_al[b * H3 + j]);
}

// ---------------- log-softmax finalize: merge tile partials + normalize ----------------
// grid (64 b, 4 segs), 256 threads
__global__ __launch_bounds__(256) void lsm_kernel(float* __restrict__ out, int step)
{
    __shared__ float sm[128];
    __shared__ int   si[128];
    __shared__ float ssum[128];

    int b = blockIdx.x;
    int seg = blockIdx.y;
    int tid = threadIdx.x;

    float m = -1e30f; int a = 0x7fffffff;
    if (tid < NTILE) { m = g_pm[tid][b]; a = g_pa[tid][b]; }
    if (tid < 128) { sm[tid] = m; si[tid] = a; }
    __syncthreads();
    for (int o = 64; o > 0; o >>= 1) {
        if (tid < o) {
            float ov = sm[tid + o]; int oi = si[tid + o];
            if (ov > sm[tid] || (ov == sm[tid] && oi < si[tid])) { sm[tid] = ov; si[tid] = oi; }
        }
        __syncthreads();
    }
    float M = sm[0];

    float s = 0.f;
    if (tid < NTILE) s = g_ps[tid][b] * expf(g_pm[tid][b] - M);
    if (tid < 128) ssum[tid] = s;
    __syncthreads();
    for (int o = 64; o > 0; o >>= 1) {
        if (tid < o) ssum[tid] += ssum[tid + o];
        __syncthreads();
    }
    float lse = M + logf(ssum[0]);

    if (seg == 0 && tid == 0) g_tok[b] = si[0];

    float* row = out + (size_t)(step * BB + b) * KY;
    int i0 = seg * (KY / 4);
    for (int i = i0 + tid; i < i0 + KY / 4; i += 256)
        row[i] -= lse;
}

// ---------------- host launch ----------------
extern "C" void kernel_launch(void* const* d_in, const int* in_sizes, int n_in,
                              void* d_out, int out_size)
{
    const int*   inputs  = (const int*)d_in[0];
    const float* enc_emb = (const float*)d_in[2];
    const float* W_ih_f  = (const float*)d_in[3];
    const float* W_hh_f  = (const float*)d_in[4];
    const float* b_ih_f  = (const float*)d_in[5];
    const float* b_hh_f  = (const float*)d_in[6];
    const float* W_ih_b  = (const float*)d_in[7];
    const float* W_hh_b  = (const float*)d_in[8];
    const float* b_ih_b  = (const float*)d_in[9];
    const float* b_hh_b  = (const float*)d_in[10];
    const float* W_init  = (const float*)d_in[11];
    const float* b_init  = (const float*)d_in[12];
    const float* dec_emb = (const float*)d_in[13];
    const float* W_ih_d  = (const float*)d_in[14];
    const float* W_hh_d  = (const float*)d_in[15];
    const float* b_ih_d  = (const float*)d_in[16];
    const float* b_hh_d  = (const float*)d_in[17];
    const float* W_lsm   = (const float*)d_in[18];
    const float* b_lsm   = (const float*)d_in[19];
    const float* W_a1    = (const float*)d_in[20];
    const float* b_a1    = (const float*)d_in[21];
    const float* W_a2    = (const float*)d_in[22];
    const float* b_a2    = (const float*)d_in[23];
    float* out = (float*)d_out;

    static float* p_P    = nullptr;
    static float* p_gi_f = nullptr;
    static float* p_gi_b = nullptr;
    static float* p_enc  = nullptr;
    static float* p_hd   = nullptr;
    static float* p_henc = nullptr;
    static float* p_q    = nullptr;
    static bool attr_done = false;
    if (!p_gi_f) {
        cudaGetSymbolAddress((void**)&p_gi_f, g_gi_f);
        cudaGetSymbolAddress((void**)&p_gi_b, g_gi_b);
        cudaGetSymbolAddress((void**)&p_enc,  g_enc);
        cudaGetSymbolAddress((void**)&p_P,    g_P);
        cudaGetSymbolAddress((void**)&p_hd,   g_hd);
        cudaGetSymbolAddress((void**)&p_henc, g_henc);
        cudaGetSymbolAddress((void**)&p_q,    g_q);
    }
    if (!attr_done) {
        cudaFuncSetAttribute(logits_mma_kernel,
                             cudaFuncAttributeMaxDynamicSharedMemorySize, LG_SMEM_TOTAL);
        cudaFuncSetAttribute(enc_persist_kernel,
                             cudaFuncAttributeMaxDynamicSharedMemorySize, ENC_SMEM);
        attr_done = true;
    }

    init_kernel<<<128, 256>>>();

    // W_lsm -> bf16 hi/lo split (once per launch)
    convw_kernel<<<(int)(((size_t)KY * H3 / 4) / 256), 256>>>(W_lsm);

    // batched input-side GRU preactivations
    sgemm_kernel<<<dim3(H3 / 128, TX * BB / 64), 256>>>(
        enc_emb, inputs, W_ih_f, EE, b_ih_f, p_gi_f, H3, EE);
    sgemm_kernel<<<dim3(H3 / 128, TX * BB / 64), 256>>>(
        enc_emb, inputs, W_ih_b, EE, b_ih_b, p_gi_b, H3, EE);

    // encoder recurrence — single persistent launch
    enc_persist_kernel<<<dim3(64, 2), 512, ENC_SMEM>>>(W_hh_f, b_hh_f, W_hh_b, b_hh_b);

    // step-invariant attention term
    sgemm_kernel<<<dim3(HH / 128, TX * BB / 64), 256>>>(
        p_enc, nullptr, W_a1 + HH, H3, b_a1, p_P, HH, CTXD);

    // decoder hidden init
    colproj_kernel<<<64, 512>>>(p_henc + 2 * BB * HH, W_init, HH, b_init, p_hd, 1);

    for (int s = 0; s < TY; s++) {
        float* hcur = p_hd + (s & 1) * BB * HH;
        colproj_kernel<<<64, 512>>>(hcur, W_a1, H3, nullptr, p_q, 0);
        attn_kernel<<<64, 256>>>(W_a2, b_a2, dec_emb);
        decgru_kernel<<<128, 256>>>(s, W_ih_d, W_hh_d, b_ih_d, b_hh_d);
        logits_mma_kernel<<<NTILE, 256, LG_SMEM_TOTAL>>>(b_lsm, out, s);
        lsm_kernel<<<dim3(64, 4), 256>>>(out, s);
    }
}